// round 5
// baseline (speedup 1.0000x reference)
#include <cuda_runtime.h>
#include <cstdint>

// ---------------- constants ----------------
#define B_   128
#define C_   64
#define S_   4096
#define NROW (B_*C_)            // 8192
#define NTOT ((size_t)B_*C_*S_) // 33554432

// ---------------- scratch (no allocation allowed) ----------------
__device__ float g_sd[NROW];        // 0.1 * per (b,c) row std (shared by both views)
__device__ int   g_shift[2*B_];     // per-view per-batch circular shift
__device__ float g_scale[2*B_];     // per-view per-batch amplitude scale
__device__ float g_mask[2*NROW];    // per-view per-(b,c) dropout mask

// ---------------- Threefry-2x32-20 (JAX-exact) ----------------
#define TF_R(x0,x1,r) { x0 += x1; x1 = __funnelshift_l(x1,x1,r); x1 ^= x0; }

__device__ __forceinline__ void tf_block(uint32_t k0, uint32_t k1,
                                         uint32_t c0, uint32_t c1,
                                         uint32_t &o0, uint32_t &o1) {
  uint32_t k2 = k0 ^ k1 ^ 0x1BD11BDAu;
  uint32_t x0 = c0 + k0, x1 = c1 + k1;
  TF_R(x0,x1,13) TF_R(x0,x1,15) TF_R(x0,x1,26) TF_R(x0,x1,6)
  x0 += k1; x1 += k2 + 1u;
  TF_R(x0,x1,17) TF_R(x0,x1,29) TF_R(x0,x1,16) TF_R(x0,x1,24)
  x0 += k2; x1 += k0 + 2u;
  TF_R(x0,x1,13) TF_R(x0,x1,15) TF_R(x0,x1,26) TF_R(x0,x1,6)
  x0 += k0; x1 += k1 + 3u;
  TF_R(x0,x1,17) TF_R(x0,x1,29) TF_R(x0,x1,16) TF_R(x0,x1,24)
  x0 += k1; x1 += k2 + 4u;
  TF_R(x0,x1,13) TF_R(x0,x1,15) TF_R(x0,x1,26) TF_R(x0,x1,6)
  o0 = x0 + k2; o1 = x1 + k0 + 5u;
}

// Partitionable-mode random_bits (32-bit), element index i: counter (0, i),
// result = bits1 ^ bits2.   [validated: noise (2^25 elems)]
__device__ __forceinline__ uint32_t xbits(uint32_t k0, uint32_t k1, uint32_t i) {
  uint32_t o0, o1;
  tf_block(k0, k1, 0u, i, o0, o1);
  return o0 ^ o1;
}

// bits -> float in [0,1): (bits>>9)|1.0f bits, bitcast, minus 1  (JAX _uniform exact)
__device__ __forceinline__ float u01(uint32_t b) {
  return __uint_as_float((b >> 9) | 0x3F800000u) - 1.0f;
}

// uniform on [lo, 1): lo = nextafter(-1,0); (hi-lo) rounds to exactly 2.0f,
// and u*2 is exact, so fma == mul+add bit-for-bit here.
__device__ __forceinline__ float u_sym(uint32_t b) {
  const float lo = -0.99999994f;  // 0xBF7FFFFF
  return fmaxf(lo, fmaf(u01(b), 2.0f, lo));
}

// XLA ErfInv32 (Giles) — matches lax.erf_inv on f32
__device__ __forceinline__ float erfinv_f(float x) {
  float w = -log1pf(-x * x);
  float p;
  if (w < 5.0f) {
    w -= 2.5f;
    p = 2.81022636e-08f;
    p = fmaf(p, w, 3.43273939e-07f);
    p = fmaf(p, w, -3.5233877e-06f);
    p = fmaf(p, w, -4.39150654e-06f);
    p = fmaf(p, w, 0.00021858087f);
    p = fmaf(p, w, -0.00125372503f);
    p = fmaf(p, w, -0.00417768164f);
    p = fmaf(p, w, 0.246640727f);
    p = fmaf(p, w, 1.50140941f);
  } else {
    w = sqrtf(w) - 3.0f;
    p = -0.000200214257f;
    p = fmaf(p, w, 0.000100950558f);
    p = fmaf(p, w, 0.00134934322f);
    p = fmaf(p, w, -0.00367342844f);
    p = fmaf(p, w, 0.00573950773f);
    p = fmaf(p, w, -0.0076224613f);
    p = fmaf(p, w, 0.00943887047f);
    p = fmaf(p, w, 1.00167406f);
    p = fmaf(p, w, 2.83297682f);
  }
  return p * x;
}

__device__ __forceinline__ float normal_from_bits(uint32_t b) {
  return 1.41421356237f * erfinv_f(u_sym(b));
}

// ---------------- setup: shifts / masks / scales ----------------
// kshA = (k1 of view0 split, k2 of view0 split) packed; kshB = same for view1.
// Per view: 8192 mask elems + 128 shifts + 128 scales = 8448 tasks
__global__ void setup_kernel(uint4 kshA, uint4 kshB, uint4 kmask, uint4 kscale) {
  for (unsigned tid = blockIdx.x * blockDim.x + threadIdx.x;
       tid < 2u * 8448u; tid += gridDim.x * blockDim.x) {
    int v = (tid >= 8448u);
    unsigned i = tid - (unsigned)v * 8448u;
    if (i < 8192u) {
      // mask: uniform(k_mask, (128,64)) > 0.1; flat element i -> counter (0, i)
      uint32_t k0 = v ? kmask.z : kmask.x, k1 = v ? kmask.w : kmask.y;
      g_mask[v * NROW + i] = (u01(xbits(k0, k1, i)) > 0.1f) ? 1.0f : 0.0f;
    } else if (i < 8320u) {
      // randint(k_shift,(128,),-50,51) — MODERN JAX:
      //   k1, k2 = split(k_shift)
      //   higher = random_bits(k1, 32, (128,)); lower = random_bits(k2, 32, (128,))
      //   off = ((higher % 101) * 68 + (lower % 101)) % 101   (68 = 2^32 mod 101)
      unsigned b = i - 8192u;
      uint4 ks = v ? kshB : kshA;           // (k1.0,k1.1,k2.0,k2.1)
      uint32_t hb = xbits(ks.x, ks.y, b);   // higher from subkey k1
      uint32_t lb = xbits(ks.z, ks.w, b);   // lower  from subkey k2
      uint32_t off = ((hb % 101u) * 68u + (lb % 101u)) % 101u;
      g_shift[v * B_ + b] = -50 + (int)off;
    } else {
      // scale: uniform(k_scale,(128,1,1),0.8,1.2); flat elem j -> counter (0, j)
      unsigned j = i - 8320u;
      uint32_t k0 = v ? kscale.z : kscale.x, k1 = v ? kscale.w : kscale.y;
      float u = u01(xbits(k0, k1, j));
      const float span = 1.2f - 0.8f;   // 0x3ECCCCCE exactly
      g_scale[v * B_ + j] = fmaxf(0.8f, __fadd_rn(__fmul_rn(u, span), 0.8f));
    }
  }
}

// ---------------- per-row std (ddof=1); roll-invariant, shared by views ----------------
__global__ void std_kernel(const float* __restrict__ x) {
  int row = blockIdx.x;
  const float4* xr = reinterpret_cast<const float4*>(x + ((size_t)row << 12));
  float s = 0.0f, q = 0.0f;
#pragma unroll
  for (int i = 0; i < 8; i++) {
    float4 v = xr[threadIdx.x + (i << 7)];
    s += (v.x + v.y) + (v.z + v.w);
    q += (v.x * v.x + v.y * v.y) + (v.z * v.z + v.w * v.w);
  }
#pragma unroll
  for (int o = 16; o; o >>= 1) {
    s += __shfl_down_sync(0xFFFFFFFFu, s, o);
    q += __shfl_down_sync(0xFFFFFFFFu, q, o);
  }
  __shared__ float ss[4], qq[4];
  int w = threadIdx.x >> 5;
  if ((threadIdx.x & 31) == 0) { ss[w] = s; qq[w] = q; }
  __syncthreads();
  if (threadIdx.x == 0) {
    s = ss[0] + ss[1] + ss[2] + ss[3];
    q = qq[0] + qq[1] + qq[2] + qq[3];
    float mean = s * (1.0f / 4096.0f);
    float var = (q - 4096.0f * mean * mean) * (1.0f / 4095.0f);
    g_sd[row] = 0.1f * sqrtf(fmaxf(var, 0.0f));
  }
}

// ---------------- main: one thread per element, both views ----------------
__global__ void __launch_bounds__(256) main_kernel(const float* __restrict__ x,
                                                   float* __restrict__ out,
                                                   uint4 knoise) {
  unsigned t = blockIdx.x * blockDim.x + threadIdx.x;   // flat (b,c,s)
  int b = t >> 18;
  int s = t & 4095;
  int row = t >> 12;                 // (b<<6)+c
  size_t base = (size_t)row << 12;
  float sd = g_sd[row];

  // view 1 and view 2: independent keys, same counter (0, t)
  uint32_t a0, a1, b0, b1;
  tf_block(knoise.x, knoise.y, 0u, t, a0, a1);
  tf_block(knoise.z, knoise.w, 0u, t, b0, b1);
  float z0 = normal_from_bits(a0 ^ a1);
  float z1 = normal_from_bits(b0 ^ b1);

  int sh0 = g_shift[b];
  int sh1 = g_shift[B_ + b];
  float xv0 = __ldg(x + base + (unsigned)((s - sh0) & 4095));
  float xv1 = __ldg(x + base + (unsigned)((s - sh1) & 4095));

  // mask in {0,1} -> (a*mask)*scale == a*(mask*scale) exactly
  float ms0 = g_mask[row]        * g_scale[b];
  float ms1 = g_mask[NROW + row] * g_scale[B_ + b];

  out[base + s]        = (xv0 + z0 * sd) * ms0;
  out[NTOT + base + s] = (xv1 + z1 * sd) * ms1;
}

// ---------------- host-side Threefry for constant key derivation ----------------
static inline uint32_t h_rotl(uint32_t x, int r) { return (x << r) | (x >> (32 - r)); }
static void h_tf(uint32_t k0, uint32_t k1, uint32_t x0, uint32_t x1,
                 uint32_t* o0, uint32_t* o1) {
  uint32_t k2 = k0 ^ k1 ^ 0x1BD11BDAu;
  x0 += k0; x1 += k1;
#define HR(r) { x0 += x1; x1 = h_rotl(x1, r); x1 ^= x0; }
  HR(13) HR(15) HR(26) HR(6)  x0 += k1; x1 += k2 + 1u;
  HR(17) HR(29) HR(16) HR(24) x0 += k2; x1 += k0 + 2u;
  HR(13) HR(15) HR(26) HR(6)  x0 += k0; x1 += k1 + 3u;
  HR(17) HR(29) HR(16) HR(24) x0 += k1; x1 += k2 + 4u;
  HR(13) HR(15) HR(26) HR(6)  x0 += k2; x1 += k0 + 5u;
#undef HR
  *o0 = x0; *o1 = x1;
}

extern "C" void kernel_launch(void* const* d_in, const int* in_sizes, int n_in,
                              void* d_out, int out_size) {
  const float* x = (const float*)d_in[0];
  float* out = (float*)d_out;

  // base = key(42) = (0, 42); view keys = fold_in(base, v) = threefry_block(base, (0, v))
  uint32_t vk[2][2];
  h_tf(0u, 42u, 0u, 1u, &vk[0][0], &vk[0][1]);
  h_tf(0u, 42u, 0u, 2u, &vk[1][0], &vk[1][1]);

  // foldlike split(key, 4): key_j = block output, counter (0, j).
  // j=0: k_shift, 1: k_noise, 2: k_mask, 3: k_scale
  uint4 kshA, kshB, knoise, kmask, kscale;
  for (int v = 0; v < 2; v++) {
    uint32_t kj[4][2];
    for (uint32_t j = 0; j < 4; j++)
      h_tf(vk[v][0], vk[v][1], 0u, j, &kj[j][0], &kj[j][1]);
    // randint's internal split(k_shift, 2): subkeys at counters (0,0) and (0,1)
    uint32_t s1[2], s2[2];
    h_tf(kj[0][0], kj[0][1], 0u, 0u, &s1[0], &s1[1]);
    h_tf(kj[0][0], kj[0][1], 0u, 1u, &s2[0], &s2[1]);
    if (v == 0) {
      kshA.x = s1[0]; kshA.y = s1[1]; kshA.z = s2[0]; kshA.w = s2[1];
      knoise.x = kj[1][0]; knoise.y = kj[1][1];
      kmask.x  = kj[2][0]; kmask.y  = kj[2][1];
      kscale.x = kj[3][0]; kscale.y = kj[3][1];
    } else {
      kshB.x = s1[0]; kshB.y = s1[1]; kshB.z = s2[0]; kshB.w = s2[1];
      knoise.z = kj[1][0]; knoise.w = kj[1][1];
      kmask.z  = kj[2][0]; kmask.w  = kj[2][1];
      kscale.z = kj[3][0]; kscale.w = kj[3][1];
    }
  }

  setup_kernel<<<66, 256>>>(kshA, kshB, kmask, kscale);
  std_kernel<<<NROW, 128>>>(x);
  main_kernel<<<(unsigned)(NTOT / 256), 256>>>(x, out, knoise);
}

// round 6
// speedup vs baseline: 1.2187x; 1.2187x over previous
#include <cuda_runtime.h>
#include <cstdint>

// ---------------- constants ----------------
#define B_   128
#define C_   64
#define S_   4096
#define NROW (B_*C_)            // 8192
#define NTOT ((size_t)B_*C_*S_) // 33554432

// ---------------- scratch (no allocation allowed) ----------------
__device__ float g_sd[NROW];        // 0.1 * per (b,c) row std (shared by both views)
__device__ int   g_shift[2*B_];     // per-view per-batch circular shift
__device__ float g_scale[2*B_];     // per-view per-batch amplitude scale
__device__ float g_mask[2*NROW];    // per-view per-(b,c) dropout mask

// ---------------- Threefry-2x32-20 (JAX-exact) ----------------
#define TF_R(x0,x1,r) { x0 += x1; x1 = __funnelshift_l(x1,x1,r); x1 ^= x0; }

// specialized: counter = (0, c1)
__device__ __forceinline__ void tf_block0(uint32_t k0, uint32_t k1,
                                          uint32_t c1,
                                          uint32_t &o0, uint32_t &o1) {
  uint32_t k2 = k0 ^ k1 ^ 0x1BD11BDAu;
  uint32_t x0 = k0, x1 = c1 + k1;
  TF_R(x0,x1,13) TF_R(x0,x1,15) TF_R(x0,x1,26) TF_R(x0,x1,6)
  x0 += k1; x1 += k2 + 1u;
  TF_R(x0,x1,17) TF_R(x0,x1,29) TF_R(x0,x1,16) TF_R(x0,x1,24)
  x0 += k2; x1 += k0 + 2u;
  TF_R(x0,x1,13) TF_R(x0,x1,15) TF_R(x0,x1,26) TF_R(x0,x1,6)
  x0 += k0; x1 += k1 + 3u;
  TF_R(x0,x1,17) TF_R(x0,x1,29) TF_R(x0,x1,16) TF_R(x0,x1,24)
  x0 += k1; x1 += k2 + 4u;
  TF_R(x0,x1,13) TF_R(x0,x1,15) TF_R(x0,x1,26) TF_R(x0,x1,6)
  o0 = x0 + k2; o1 = x1 + k0 + 5u;
}

// Partitionable-mode random_bits (32-bit), element index i: counter (0, i),
// result = bits1 ^ bits2.   [validated]
__device__ __forceinline__ uint32_t xbits(uint32_t k0, uint32_t k1, uint32_t i) {
  uint32_t o0, o1;
  tf_block0(k0, k1, i, o0, o1);
  return o0 ^ o1;
}

// bits -> float in [0,1): (bits>>9)|1.0f bits, bitcast, minus 1  (JAX _uniform exact)
__device__ __forceinline__ float u01(uint32_t b) {
  return __uint_as_float((b >> 9) | 0x3F800000u) - 1.0f;
}

// normal = sqrt(2)*erfinv(u) with u on [lo,1), lo=nextafter(-1,0).
// Fast variant: -__logf(1-x*x) instead of -log1pf(-x*x); |Δw|~1e-7 -> |Δz| ≪ 1e-5,
// far inside the 1e-3 rel budget (noise is a 0.1x contribution anyway).
__device__ __forceinline__ float normal_from_bits(uint32_t bts) {
  const float lo = -0.99999994f;  // 0xBF7FFFFF
  float x = fmaxf(lo, fmaf(u01(bts), 2.0f, lo));
  float w = -__logf(1.0f - x * x);
  float p;
  if (w < 5.0f) {
    w -= 2.5f;
    p = 2.81022636e-08f;
    p = fmaf(p, w, 3.43273939e-07f);
    p = fmaf(p, w, -3.5233877e-06f);
    p = fmaf(p, w, -4.39150654e-06f);
    p = fmaf(p, w, 0.00021858087f);
    p = fmaf(p, w, -0.00125372503f);
    p = fmaf(p, w, -0.00417768164f);
    p = fmaf(p, w, 0.246640727f);
    p = fmaf(p, w, 1.50140941f);
  } else {
    w = sqrtf(w) - 3.0f;
    p = -0.000200214257f;
    p = fmaf(p, w, 0.000100950558f);
    p = fmaf(p, w, 0.00134934322f);
    p = fmaf(p, w, -0.00367342844f);
    p = fmaf(p, w, 0.00573950773f);
    p = fmaf(p, w, -0.0076224613f);
    p = fmaf(p, w, 0.00943887047f);
    p = fmaf(p, w, 1.00167406f);
    p = fmaf(p, w, 2.83297682f);
  }
  return 1.41421356237f * (p * x);
}

// ---------------- fused prep: per-row std + shifts/masks/scales ----------------
// 8192 blocks x 128 threads. Each block reduces one row; global threads
// 0..16895 additionally produce the setup tables.
__global__ void prep_kernel(const float* __restrict__ x,
                            uint4 kshA, uint4 kshB, uint4 kmask, uint4 kscale) {
  // ---- setup part (first 16896 global threads; one task each) ----
  unsigned gt = blockIdx.x * blockDim.x + threadIdx.x;
  if (gt < 2u * 8448u) {
    int v = (gt >= 8448u);
    unsigned i = gt - (unsigned)v * 8448u;
    if (i < 8192u) {
      uint32_t k0 = v ? kmask.z : kmask.x, k1 = v ? kmask.w : kmask.y;
      g_mask[v * NROW + i] = (u01(xbits(k0, k1, i)) > 0.1f) ? 1.0f : 0.0f;
    } else if (i < 8320u) {
      // randint(k_shift,(128,),-50,51): k1,k2 = split(k_shift);
      // higher from k1, lower from k2; 68 = 2^32 mod 101
      unsigned b = i - 8192u;
      uint4 ks = v ? kshB : kshA;
      uint32_t hb = xbits(ks.x, ks.y, b);
      uint32_t lb = xbits(ks.z, ks.w, b);
      uint32_t off = ((hb % 101u) * 68u + (lb % 101u)) % 101u;
      g_shift[v * B_ + b] = -50 + (int)off;
    } else {
      unsigned j = i - 8320u;
      uint32_t k0 = v ? kscale.z : kscale.x, k1 = v ? kscale.w : kscale.y;
      float u = u01(xbits(k0, k1, j));
      const float span = 1.2f - 0.8f;
      g_scale[v * B_ + j] = fmaxf(0.8f, __fadd_rn(__fmul_rn(u, span), 0.8f));
    }
  }

  // ---- std part: one row per block ----
  int row = blockIdx.x;
  const float4* xr = reinterpret_cast<const float4*>(x + ((size_t)row << 12));
  float s = 0.0f, q = 0.0f;
#pragma unroll
  for (int i = 0; i < 8; i++) {
    float4 v = xr[threadIdx.x + (i << 7)];
    s += (v.x + v.y) + (v.z + v.w);
    q += (v.x * v.x + v.y * v.y) + (v.z * v.z + v.w * v.w);
  }
#pragma unroll
  for (int o = 16; o; o >>= 1) {
    s += __shfl_down_sync(0xFFFFFFFFu, s, o);
    q += __shfl_down_sync(0xFFFFFFFFu, q, o);
  }
  __shared__ float ss[4], qq[4];
  int w = threadIdx.x >> 5;
  if ((threadIdx.x & 31) == 0) { ss[w] = s; qq[w] = q; }
  __syncthreads();
  if (threadIdx.x == 0) {
    s = ss[0] + ss[1] + ss[2] + ss[3];
    q = qq[0] + qq[1] + qq[2] + qq[3];
    float mean = s * (1.0f / 4096.0f);
    float var = (q - 4096.0f * mean * mean) * (1.0f / 4095.0f);
    g_sd[row] = 0.1f * sqrtf(fmaxf(var, 0.0f));
  }
}

// ---------------- main: 4 consecutive elements per thread, both views ----------------
__global__ void __launch_bounds__(256) main_kernel(const float* __restrict__ x,
                                                   float* __restrict__ out,
                                                   uint4 knoise) {
  unsigned t0 = (blockIdx.x * blockDim.x + threadIdx.x) * 4u;  // flat (b,c,s), s%4==0
  int b = t0 >> 18;
  int s0 = t0 & 4095;
  int row = t0 >> 12;
  size_t base = (size_t)row << 12;
  float sd = g_sd[row];
  int sh0 = g_shift[b];
  int sh1 = g_shift[B_ + b];
  float ms0 = g_mask[row]        * g_scale[b];
  float ms1 = g_mask[NROW + row] * g_scale[B_ + b];

  float4 o0, o1;
  float* p0 = &o0.x;
  float* p1 = &o1.x;
#pragma unroll
  for (int j = 0; j < 4; j++) {
    uint32_t a0, a1, c0, c1;
    tf_block0(knoise.x, knoise.y, t0 + j, a0, a1);
    tf_block0(knoise.z, knoise.w, t0 + j, c0, c1);
    float z0 = normal_from_bits(a0 ^ a1);
    float z1 = normal_from_bits(c0 ^ c1);
    float xv0 = __ldg(x + base + (unsigned)((s0 + j - sh0) & 4095));
    float xv1 = __ldg(x + base + (unsigned)((s0 + j - sh1) & 4095));
    p0[j] = (xv0 + z0 * sd) * ms0;
    p1[j] = (xv1 + z1 * sd) * ms1;
  }

  *reinterpret_cast<float4*>(out + base + s0)        = o0;
  *reinterpret_cast<float4*>(out + NTOT + base + s0) = o1;
}

// ---------------- host-side Threefry for constant key derivation ----------------
static inline uint32_t h_rotl(uint32_t x, int r) { return (x << r) | (x >> (32 - r)); }
static void h_tf(uint32_t k0, uint32_t k1, uint32_t x0, uint32_t x1,
                 uint32_t* o0, uint32_t* o1) {
  uint32_t k2 = k0 ^ k1 ^ 0x1BD11BDAu;
  x0 += k0; x1 += k1;
#define HR(r) { x0 += x1; x1 = h_rotl(x1, r); x1 ^= x0; }
  HR(13) HR(15) HR(26) HR(6)  x0 += k1; x1 += k2 + 1u;
  HR(17) HR(29) HR(16) HR(24) x0 += k2; x1 += k0 + 2u;
  HR(13) HR(15) HR(26) HR(6)  x0 += k0; x1 += k1 + 3u;
  HR(17) HR(29) HR(16) HR(24) x0 += k1; x1 += k2 + 4u;
  HR(13) HR(15) HR(26) HR(6)  x0 += k2; x1 += k0 + 5u;
#undef HR
  *o0 = x0; *o1 = x1;
}

extern "C" void kernel_launch(void* const* d_in, const int* in_sizes, int n_in,
                              void* d_out, int out_size) {
  const float* x = (const float*)d_in[0];
  float* out = (float*)d_out;

  // base = key(42) = (0, 42); view keys = fold_in(base, v) = threefry_block(base, (0, v))
  uint32_t vk[2][2];
  h_tf(0u, 42u, 0u, 1u, &vk[0][0], &vk[0][1]);
  h_tf(0u, 42u, 0u, 2u, &vk[1][0], &vk[1][1]);

  // foldlike split(key, 4): key_j = block output, counter (0, j).
  // j=0: k_shift, 1: k_noise, 2: k_mask, 3: k_scale
  uint4 kshA, kshB, knoise, kmask, kscale;
  for (int v = 0; v < 2; v++) {
    uint32_t kj[4][2];
    for (uint32_t j = 0; j < 4; j++)
      h_tf(vk[v][0], vk[v][1], 0u, j, &kj[j][0], &kj[j][1]);
    // randint's internal split(k_shift, 2): subkeys at counters (0,0) and (0,1)
    uint32_t s1[2], s2[2];
    h_tf(kj[0][0], kj[0][1], 0u, 0u, &s1[0], &s1[1]);
    h_tf(kj[0][0], kj[0][1], 0u, 1u, &s2[0], &s2[1]);
    if (v == 0) {
      kshA.x = s1[0]; kshA.y = s1[1]; kshA.z = s2[0]; kshA.w = s2[1];
      knoise.x = kj[1][0]; knoise.y = kj[1][1];
      kmask.x  = kj[2][0]; kmask.y  = kj[2][1];
      kscale.x = kj[3][0]; kscale.y = kj[3][1];
    } else {
      kshB.x = s1[0]; kshB.y = s1[1]; kshB.z = s2[0]; kshB.w = s2[1];
      knoise.z = kj[1][0]; knoise.w = kj[1][1];
      kmask.z  = kj[2][0]; kmask.w  = kj[2][1];
      kscale.z = kj[3][0]; kscale.w = kj[3][1];
    }
  }

  prep_kernel<<<NROW, 128>>>(x, kshA, kshB, kmask, kscale);
  main_kernel<<<(unsigned)(NTOT / 4 / 256), 256>>>(x, out, knoise);
}

// round 7
// speedup vs baseline: 1.3394x; 1.0990x over previous
#include <cuda_runtime.h>
#include <cstdint>

// ---------------- constants ----------------
#define B_   128
#define C_   64
#define S_   4096
#define NROW (B_*C_)            // 8192
#define NTOT ((size_t)B_*C_*S_) // 33554432

// ---------------- scratch (no allocation allowed) ----------------
__device__ float g_sd[NROW];        // sqrt2 * 0.1 * per-row std (shared by views)
__device__ int   g_shift[2*B_];
__device__ float g_scale[2*B_];
__device__ float g_mask[2*NROW];

// ---------------- Threefry-2x32-20 (JAX-exact) ----------------
#define TF_R(x0,x1,r) { x0 += x1; x1 = __funnelshift_l(x1,x1,r); x1 ^= x0; }

// plain version (prep kernel, low volume)
__device__ __forceinline__ void tf_block0(uint32_t k0, uint32_t k1,
                                          uint32_t c1,
                                          uint32_t &o0, uint32_t &o1) {
  uint32_t k2 = k0 ^ k1 ^ 0x1BD11BDAu;
  uint32_t x0 = k0, x1 = c1 + k1;
  TF_R(x0,x1,13) TF_R(x0,x1,15) TF_R(x0,x1,26) TF_R(x0,x1,6)
  x0 += k1; x1 += k2 + 1u;
  TF_R(x0,x1,17) TF_R(x0,x1,29) TF_R(x0,x1,16) TF_R(x0,x1,24)
  x0 += k2; x1 += k0 + 2u;
  TF_R(x0,x1,13) TF_R(x0,x1,15) TF_R(x0,x1,26) TF_R(x0,x1,6)
  x0 += k0; x1 += k1 + 3u;
  TF_R(x0,x1,17) TF_R(x0,x1,29) TF_R(x0,x1,16) TF_R(x0,x1,24)
  x0 += k1; x1 += k2 + 4u;
  TF_R(x0,x1,13) TF_R(x0,x1,15) TF_R(x0,x1,26) TF_R(x0,x1,6)
  o0 = x0 + k2; o1 = x1 + k0 + 5u;
}

// fma-pipe-balanced version: adds emitted as IMAD via runtime `one`
// (mad.lo.u32 d, a, one, d  ->  d = a*one + d; one==1 at runtime, not foldable)
#define MAD1(d,a) asm("mad.lo.u32 %0, %1, %2, %0;" : "+r"(d) : "r"(a), "r"(one))
#define TF_RM(x0,x1,r) { MAD1(x0,x1); x1 = __funnelshift_l(x1,x1,r); x1 ^= x0; }

__device__ __forceinline__ void tf_fast(uint32_t k0, uint32_t k1,
                                        uint32_t c1, uint32_t one,
                                        uint32_t &o0, uint32_t &o1) {
  uint32_t k2 = k0 ^ k1 ^ 0x1BD11BDAu;
  uint32_t i1 = k2 + 1u, i2 = k0 + 2u, i3 = k1 + 3u, i4 = k2 + 4u, i5 = k0 + 5u;
  uint32_t x0 = k0, x1 = c1 + k1;
  TF_RM(x0,x1,13) TF_RM(x0,x1,15) TF_RM(x0,x1,26) TF_RM(x0,x1,6)
  MAD1(x0, k1); MAD1(x1, i1);
  TF_RM(x0,x1,17) TF_RM(x0,x1,29) TF_RM(x0,x1,16) TF_RM(x0,x1,24)
  MAD1(x0, k2); MAD1(x1, i2);
  TF_RM(x0,x1,13) TF_RM(x0,x1,15) TF_RM(x0,x1,26) TF_RM(x0,x1,6)
  MAD1(x0, k0); MAD1(x1, i3);
  TF_RM(x0,x1,17) TF_RM(x0,x1,29) TF_RM(x0,x1,16) TF_RM(x0,x1,24)
  MAD1(x0, k1); MAD1(x1, i4);
  TF_RM(x0,x1,13) TF_RM(x0,x1,15) TF_RM(x0,x1,26) TF_RM(x0,x1,6)
  MAD1(x0, k2); MAD1(x1, i5);
  o0 = x0; o1 = x1;
}

__device__ __forceinline__ uint32_t xbits(uint32_t k0, uint32_t k1, uint32_t i) {
  uint32_t o0, o1;
  tf_block0(k0, k1, i, o0, o1);
  return o0 ^ o1;
}

// bits -> float in [0,1): (bits>>9)|1.0f bits, bitcast, minus 1  (JAX _uniform exact)
__device__ __forceinline__ float u01(uint32_t b) {
  return __uint_as_float((b >> 9) | 0x3F800000u) - 1.0f;
}

// erfinv(u_sym(bits)) WITHOUT the sqrt(2) (folded into sd).
// u>=0 makes the reference's max(lo, .) a provable no-op; dropped.
// -__logf(1-x^2) vs -log1pf: |Δ| ~1e-7 in w -> ~1e-6 in z, vs 1e-3 budget.
__device__ __forceinline__ float erfinv_from_bits(uint32_t bts) {
  const float lo = -0.99999994f;  // 0xBF7FFFFF
  float x = fmaf(u01(bts), 2.0f, lo);
  float w = -__logf(1.0f - x * x);
  float p;
  if (w < 5.0f) {
    w -= 2.5f;
    p = 2.81022636e-08f;
    p = fmaf(p, w, 3.43273939e-07f);
    p = fmaf(p, w, -3.5233877e-06f);
    p = fmaf(p, w, -4.39150654e-06f);
    p = fmaf(p, w, 0.00021858087f);
    p = fmaf(p, w, -0.00125372503f);
    p = fmaf(p, w, -0.00417768164f);
    p = fmaf(p, w, 0.246640727f);
    p = fmaf(p, w, 1.50140941f);
  } else {
    w = sqrtf(w) - 3.0f;
    p = -0.000200214257f;
    p = fmaf(p, w, 0.000100950558f);
    p = fmaf(p, w, 0.00134934322f);
    p = fmaf(p, w, -0.00367342844f);
    p = fmaf(p, w, 0.00573950773f);
    p = fmaf(p, w, -0.0076224613f);
    p = fmaf(p, w, 0.00943887047f);
    p = fmaf(p, w, 1.00167406f);
    p = fmaf(p, w, 2.83297682f);
  }
  return p * x;
}

// ---------------- fused prep: per-row std + shifts/masks/scales ----------------
__global__ void prep_kernel(const float* __restrict__ x,
                            uint4 kshA, uint4 kshB, uint4 kmask, uint4 kscale) {
  unsigned gt = blockIdx.x * blockDim.x + threadIdx.x;
  if (gt < 2u * 8448u) {
    int v = (gt >= 8448u);
    unsigned i = gt - (unsigned)v * 8448u;
    if (i < 8192u) {
      uint32_t k0 = v ? kmask.z : kmask.x, k1 = v ? kmask.w : kmask.y;
      g_mask[v * NROW + i] = (u01(xbits(k0, k1, i)) > 0.1f) ? 1.0f : 0.0f;
    } else if (i < 8320u) {
      // randint: k1,k2 = split(k_shift); higher from k1, lower from k2; 68 = 2^32 % 101
      unsigned b = i - 8192u;
      uint4 ks = v ? kshB : kshA;
      uint32_t hb = xbits(ks.x, ks.y, b);
      uint32_t lb = xbits(ks.z, ks.w, b);
      uint32_t off = ((hb % 101u) * 68u + (lb % 101u)) % 101u;
      g_shift[v * B_ + b] = -50 + (int)off;
    } else {
      unsigned j = i - 8320u;
      uint32_t k0 = v ? kscale.z : kscale.x, k1 = v ? kscale.w : kscale.y;
      float u = u01(xbits(k0, k1, j));
      const float span = 1.2f - 0.8f;
      g_scale[v * B_ + j] = fmaxf(0.8f, __fadd_rn(__fmul_rn(u, span), 0.8f));
    }
  }

  int row = blockIdx.x;
  const float4* xr = reinterpret_cast<const float4*>(x + ((size_t)row << 12));
  float s = 0.0f, q = 0.0f;
#pragma unroll
  for (int i = 0; i < 8; i++) {
    float4 v = xr[threadIdx.x + (i << 7)];
    s += (v.x + v.y) + (v.z + v.w);
    q += (v.x * v.x + v.y * v.y) + (v.z * v.z + v.w * v.w);
  }
#pragma unroll
  for (int o = 16; o; o >>= 1) {
    s += __shfl_down_sync(0xFFFFFFFFu, s, o);
    q += __shfl_down_sync(0xFFFFFFFFu, q, o);
  }
  __shared__ float ss[4], qq[4];
  int w = threadIdx.x >> 5;
  if ((threadIdx.x & 31) == 0) { ss[w] = s; qq[w] = q; }
  __syncthreads();
  if (threadIdx.x == 0) {
    s = ss[0] + ss[1] + ss[2] + ss[3];
    q = qq[0] + qq[1] + qq[2] + qq[3];
    float mean = s * (1.0f / 4096.0f);
    float var = (q - 4096.0f * mean * mean) * (1.0f / 4095.0f);
    // fold 0.1 (NOISE_STD) and sqrt(2) (from normal) into one factor
    g_sd[row] = 0.141421356237f * sqrtf(fmaxf(var, 0.0f));
  }
}

// ---------------- main: 4 consecutive elements per thread, both views ----------------
__global__ void __launch_bounds__(256) main_kernel(const float* __restrict__ x,
                                                   float* __restrict__ out,
                                                   uint4 knoise, uint32_t one) {
  unsigned t0 = (blockIdx.x * blockDim.x + threadIdx.x) * 4u;  // s%4==0
  int b = t0 >> 18;
  int s0 = t0 & 4095;
  int row = t0 >> 12;
  size_t base = (size_t)row << 12;
  float sd = g_sd[row];
  int sh0 = g_shift[b];
  int sh1 = g_shift[B_ + b];
  float ms0 = g_mask[row]        * g_scale[b];
  float ms1 = g_mask[NROW + row] * g_scale[B_ + b];

  float4 o0, o1;
  float* p0 = &o0.x;
  float* p1 = &o1.x;
#pragma unroll
  for (int j = 0; j < 4; j++) {
    uint32_t a0, a1, c0, c1;
    tf_fast(knoise.x, knoise.y, t0 + j, one, a0, a1);
    tf_fast(knoise.z, knoise.w, t0 + j, one, c0, c1);
    float z0 = erfinv_from_bits(a0 ^ a1);
    float z1 = erfinv_from_bits(c0 ^ c1);
    float xv0 = __ldg(x + base + (unsigned)((s0 + j - sh0) & 4095));
    float xv1 = __ldg(x + base + (unsigned)((s0 + j - sh1) & 4095));
    p0[j] = (xv0 + z0 * sd) * ms0;
    p1[j] = (xv1 + z1 * sd) * ms1;
  }

  *reinterpret_cast<float4*>(out + base + s0)        = o0;
  *reinterpret_cast<float4*>(out + NTOT + base + s0) = o1;
}

// ---------------- host-side Threefry for constant key derivation ----------------
static inline uint32_t h_rotl(uint32_t x, int r) { return (x << r) | (x >> (32 - r)); }
static void h_tf(uint32_t k0, uint32_t k1, uint32_t x0, uint32_t x1,
                 uint32_t* o0, uint32_t* o1) {
  uint32_t k2 = k0 ^ k1 ^ 0x1BD11BDAu;
  x0 += k0; x1 += k1;
#define HR(r) { x0 += x1; x1 = h_rotl(x1, r); x1 ^= x0; }
  HR(13) HR(15) HR(26) HR(6)  x0 += k1; x1 += k2 + 1u;
  HR(17) HR(29) HR(16) HR(24) x0 += k2; x1 += k0 + 2u;
  HR(13) HR(15) HR(26) HR(6)  x0 += k0; x1 += k1 + 3u;
  HR(17) HR(29) HR(16) HR(24) x0 += k1; x1 += k2 + 4u;
  HR(13) HR(15) HR(26) HR(6)  x0 += k2; x1 += k0 + 5u;
#undef HR
  *o0 = x0; *o1 = x1;
}

extern "C" void kernel_launch(void* const* d_in, const int* in_sizes, int n_in,
                              void* d_out, int out_size) {
  const float* x = (const float*)d_in[0];
  float* out = (float*)d_out;

  uint32_t vk[2][2];
  h_tf(0u, 42u, 0u, 1u, &vk[0][0], &vk[0][1]);
  h_tf(0u, 42u, 0u, 2u, &vk[1][0], &vk[1][1]);

  uint4 kshA, kshB, knoise, kmask, kscale;
  for (int v = 0; v < 2; v++) {
    uint32_t kj[4][2];
    for (uint32_t j = 0; j < 4; j++)
      h_tf(vk[v][0], vk[v][1], 0u, j, &kj[j][0], &kj[j][1]);
    uint32_t s1[2], s2[2];
    h_tf(kj[0][0], kj[0][1], 0u, 0u, &s1[0], &s1[1]);
    h_tf(kj[0][0], kj[0][1], 0u, 1u, &s2[0], &s2[1]);
    if (v == 0) {
      kshA.x = s1[0]; kshA.y = s1[1]; kshA.z = s2[0]; kshA.w = s2[1];
      knoise.x = kj[1][0]; knoise.y = kj[1][1];
      kmask.x  = kj[2][0]; kmask.y  = kj[2][1];
      kscale.x = kj[3][0]; kscale.y = kj[3][1];
    } else {
      kshB.x = s1[0]; kshB.y = s1[1]; kshB.z = s2[0]; kshB.w = s2[1];
      knoise.z = kj[1][0]; knoise.w = kj[1][1];
      kmask.z  = kj[2][0]; kmask.w  = kj[2][1];
      kscale.z = kj[3][0]; kscale.w = kj[3][1];
    }
  }

  prep_kernel<<<NROW, 128>>>(x, kshA, kshB, kmask, kscale);
  main_kernel<<<(unsigned)(NTOT / 4 / 256), 256>>>(x, out, knoise, 1u);
}